// round 1
// baseline (speedup 1.0000x reference)
#include <cuda_runtime.h>
#include <math.h>

#define BB 4
#define NN 4096
#define EE 256
#define FF 256
#define MAXE 50
#define OUTW 512

// ---------------- scratch (device globals: allocation-free) ----------------
__device__ float g_xp [BB * NN * FF];   // x @ Wn_w + Wn_b   [b][n][f]
__device__ float g_xpT[BB * FF * NN];   // transposed        [b][f][n]
__device__ float g_xw [BB * NN * FF];   // x @ weight        [b][n][f]
__device__ float g_ctx[BB * MAXE];
__device__ int   g_deg[MAXE];

// ---------------- kernel 1: fused projections -------------------------------
// xs tile 64x256 (64KB) + ws k-tile 32x256 (32KB) -> 96KB smem, 2 CTA/SM
#define PROJ_SMEM ((64 * 256 + 32 * 256) * 4)

__global__ void __launch_bounds__(256, 2)
proj_kernel(const float* __restrict__ x,
            const float* __restrict__ Wn_w, const float* __restrict__ Wn_b,
            const float* __restrict__ weight) {
    extern __shared__ float sm[];
    float* xs = sm;            // [64][256]
    float* ws = sm + 64 * 256; // [32][256]
    const int row0 = blockIdx.x * 64;           // flattened over b*n (16384 rows)
    const int tid = threadIdx.x;
    const int ty = tid >> 4, tx = tid & 15;

    {   // load x tile (coalesced float4)
        const float4* src = (const float4*)(x + (size_t)row0 * FF);
        float4* dst = (float4*)xs;
#pragma unroll
        for (int i = 0; i < 16; i++) dst[tid + i * 256] = src[tid + i * 256];
    }

    for (int wsel = 0; wsel < 2; wsel++) {
        const float* W = wsel ? weight : Wn_w;
        float acc[4][16];
#pragma unroll
        for (int i = 0; i < 4; i++)
#pragma unroll
            for (int c = 0; c < 16; c++) acc[i][c] = 0.f;

        for (int ko = 0; ko < FF; ko += 32) {
            __syncthreads();   // protect ws (and xs on first pass)
            {
                const float4* wsrc = (const float4*)(W + (size_t)ko * FF);
                float4* wdst = (float4*)ws;
#pragma unroll
                for (int i = 0; i < 8; i++) wdst[tid + i * 256] = wsrc[tid + i * 256];
            }
            __syncthreads();
#pragma unroll 2
            for (int kk = 0; kk < 32; kk++) {
                float p[4];
#pragma unroll
                for (int i = 0; i < 4; i++) p[i] = xs[(ty * 4 + i) * FF + ko + kk];
                float v[16];
                const float* vr = ws + kk * FF + tx * 16;
                *(float4*)(v + 0)  = *(const float4*)(vr + 0);
                *(float4*)(v + 4)  = *(const float4*)(vr + 4);
                *(float4*)(v + 8)  = *(const float4*)(vr + 8);
                *(float4*)(v + 12) = *(const float4*)(vr + 12);
#pragma unroll
                for (int i = 0; i < 4; i++)
#pragma unroll
                    for (int c = 0; c < 16; c++)
                        acc[i][c] = fmaf(p[i], v[c], acc[i][c]);
            }
        }
        // epilogue (global only; next wsel re-syncs before touching smem)
#pragma unroll
        for (int i = 0; i < 4; i++) {
            size_t r = (size_t)row0 + ty * 4 + i;
#pragma unroll
            for (int c4 = 0; c4 < 4; c4++) {
                int c = tx * 16 + c4 * 4;
                float4 o;
                if (wsel == 0) {
                    o.x = acc[i][c4 * 4 + 0] + Wn_b[c + 0];
                    o.y = acc[i][c4 * 4 + 1] + Wn_b[c + 1];
                    o.z = acc[i][c4 * 4 + 2] + Wn_b[c + 2];
                    o.w = acc[i][c4 * 4 + 3] + Wn_b[c + 3];
                    *(float4*)(g_xp + r * FF + c) = o;
                } else {
                    o.x = acc[i][c4 * 4 + 0];
                    o.y = acc[i][c4 * 4 + 1];
                    o.z = acc[i][c4 * 4 + 2];
                    o.w = acc[i][c4 * 4 + 3];
                    *(float4*)(g_xw + r * FF + c) = o;
                }
            }
        }
    }
}

// ---------------- kernel 2: transpose xp -> xpT ------------------------------
__global__ void transpose_kernel() {
    __shared__ float t[32][33];
    const int b = blockIdx.z;
    const int n0 = blockIdx.x * 32, f0 = blockIdx.y * 32;
    const int lx = threadIdx.x, ly = threadIdx.y;  // 32 x 8
    const float* src = g_xp + (size_t)b * NN * FF;
    float* dst = g_xpT + (size_t)b * FF * NN;
#pragma unroll
    for (int i = ly; i < 32; i += 8)
        t[i][lx] = src[(size_t)(n0 + i) * FF + f0 + lx];
    __syncthreads();
#pragma unroll
    for (int i = ly; i < 32; i += 8)
        dst[(size_t)(f0 + i) * NN + n0 + lx] = t[lx][i];
}

// ---------------- kernel 3: hyperedge branch ---------------------------------
__global__ void hedge_kernel(const float* __restrict__ x, const int* __restrict__ H,
                             const float* __restrict__ m1_w, const float* __restrict__ m1_b,
                             const float* __restrict__ m2_w, const float* __restrict__ m2_b,
                             const float* __restrict__ m3_w, const float* __restrict__ m3_b) {
    __shared__ int   flags[256];
    __shared__ float mean[FF];
    __shared__ float h1[128];
    __shared__ float h2[64];
    const int e = blockIdx.x;        // 0..49
    const int b = blockIdx.y;        // 0..3
    const int tid = threadIdx.x;     // 256 threads; thread == feature column
    const float* xb = x + (size_t)b * NN * FF;

    float a = 0.f;
    int deg = 0;
    for (int n0 = 0; n0 < NN; n0 += 256) {
        __syncthreads();
        flags[tid] = H[(size_t)(n0 + tid) * EE + e];
        __syncthreads();
#pragma unroll 8
        for (int j = 0; j < 256; j++) {
            deg += flags[j];
            if (flags[j]) a += xb[(size_t)(n0 + j) * FF + tid];
        }
    }
    mean[tid] = a / fmaxf((float)deg, 1.0f);
    __syncthreads();

    if (tid < 128) {
        float s = m1_b[tid];
#pragma unroll 4
        for (int k = 0; k < 256; k++) s = fmaf(mean[k], m1_w[k * 128 + tid], s);
        h1[tid] = fmaxf(s, 0.f);
    }
    __syncthreads();
    if (tid < 64) {
        float s = m2_b[tid];
#pragma unroll 4
        for (int k = 0; k < 128; k++) s = fmaf(h1[k], m2_w[k * 64 + tid], s);
        h2[tid] = fmaxf(s, 0.f);
    }
    __syncthreads();
    if (tid == 0) {
        float s = m3_b[0];
        for (int k = 0; k < 64; k++) s = fmaf(h2[k], m3_w[k], s);
        g_ctx[b * MAXE + e] = s;
        if (b == 0) g_deg[e] = deg;
    }
}

// ---------------- kernel 4: adaptive weights (output cols 0..255) ------------
__global__ void gamma_kernel(const float* __restrict__ x, const int* __restrict__ H,
                             const float* __restrict__ c_w, const float* __restrict__ c_b,
                             const float* __restrict__ hedge_bias, const float* __restrict__ alpha,
                             float* __restrict__ out) {
    __shared__ float red[8];
    const int n = blockIdx.x, b = blockIdx.y;
    const int tid = threadIdx.x;
    const int lane = tid & 31, warp = tid >> 5;

    float v = x[((size_t)b * NN + n) * FF + tid] * c_w[tid];
#pragma unroll
    for (int o = 16; o; o >>= 1) v += __shfl_xor_sync(0xffffffffu, v, o);
    if (lane == 0) red[warp] = v;
    __syncthreads();
    float compat = red[0] + red[1] + red[2] + red[3] + red[4] + red[5] + red[6] + red[7];
    compat += c_b[0] + hedge_bias[0];

    float o = 0.f;
    if (tid < MAXE) {
        if (g_deg[tid] > 1 && H[(size_t)n * EE + tid] != 0) {
            float z = compat + alpha[0] * g_ctx[b * MAXE + tid];
            o = 1.0f / (1.0f + expf(-z));
        }
    }
    out[((size_t)b * NN + n) * OUTW + tid] = o;
}

// ---------------- kernel 5: attention (output cols 256..511) -----------------
// BM=BN=64, 256 threads, 16x16 thread grid. Scores are O(1) -> no max-sub softmax.
#define ATTN_SW 68
#define ATTN_SMEM ((256 * 64 + 256 * 64 + 64 * 256 + 64 * ATTN_SW + 64) * 4)

__global__ void __launch_bounds__(256, 1)
attn_kernel(const float* __restrict__ bias, float* __restrict__ out) {
    extern __shared__ float sm[];
    float* Qt   = sm;                       // [256][64] k-major
    float* Kt   = Qt + FF * 64;             // [256][64] k-major
    float* Vs   = Kt + FF * 64;             // [64][256] row-major
    float* Ss   = Vs + 64 * FF;             // [64][68]
    float* lsum = Ss + 64 * ATTN_SW;        // [64]

    const int b  = blockIdx.y;
    const int m0 = blockIdx.x * 64;
    const int tid = threadIdx.x;
    const int ty = tid >> 4, tx = tid & 15;
    const int lane = tid & 31, warp = tid >> 5;

    const float* xpTb = g_xpT + (size_t)b * FF * NN;
    const float* xwb  = g_xw  + (size_t)b * NN * FF;

    // load Q tile (transposed layout: conflict-free stores & float4 reads)
    {
        float4* q4 = (float4*)Qt;
#pragma unroll
        for (int i = 0; i < 16; i++) {
            int idx = tid + i * 256;           // 0..4095 float4s
            int f = idx >> 4, r4 = idx & 15;
            q4[idx] = *(const float4*)(xpTb + (size_t)f * NN + m0 + r4 * 4);
        }
    }
    if (tid < 64) lsum[tid] = 0.f;
    float acc[4][16];
#pragma unroll
    for (int i = 0; i < 4; i++)
#pragma unroll
        for (int c = 0; c < 16; c++) acc[i][c] = 0.f;
    __syncthreads();

    for (int j0 = 0; j0 < NN; j0 += 64) {
        // ---- load K,V tiles ----
        {
            float4* k4 = (float4*)Kt;
#pragma unroll
            for (int i = 0; i < 16; i++) {
                int idx = tid + i * 256;
                int f = idx >> 4, r4 = idx & 15;
                k4[idx] = *(const float4*)(xpTb + (size_t)f * NN + j0 + r4 * 4);
            }
            float4* v4 = (float4*)Vs;
            const float4* vsrc = (const float4*)(xwb + (size_t)j0 * FF);
#pragma unroll
            for (int i = 0; i < 16; i++) v4[tid + i * 256] = vsrc[tid + i * 256];
        }
        __syncthreads();

        // ---- S = Q K^T / 16 ----
        float s[4][4];
#pragma unroll
        for (int i = 0; i < 4; i++)
#pragma unroll
            for (int j = 0; j < 4; j++) s[i][j] = 0.f;
#pragma unroll 4
        for (int k = 0; k < FF; k++) {
            float4 qf = *(const float4*)(Qt + k * 64 + ty * 4);
            float4 kf = *(const float4*)(Kt + k * 64 + tx * 4);
            float qa[4] = {qf.x, qf.y, qf.z, qf.w};
            float ka[4] = {kf.x, kf.y, kf.z, kf.w};
#pragma unroll
            for (int i = 0; i < 4; i++)
#pragma unroll
                for (int j = 0; j < 4; j++)
                    s[i][j] = fmaf(qa[i], ka[j], s[i][j]);
        }
#pragma unroll
        for (int i = 0; i < 4; i++) {
            float4 w;
            w.x = s[i][0] * 0.0625f; w.y = s[i][1] * 0.0625f;
            w.z = s[i][2] * 0.0625f; w.w = s[i][3] * 0.0625f;
            *(float4*)(Ss + (ty * 4 + i) * ATTN_SW + tx * 4) = w;
        }
        __syncthreads();

        // ---- exp + row sums (scores are O(1): no max subtraction needed) ----
#pragma unroll
        for (int rr = 0; rr < 8; rr++) {
            int r = warp * 8 + rr;
            float v0 = __expf(Ss[r * ATTN_SW + lane]);
            float v1 = __expf(Ss[r * ATTN_SW + lane + 32]);
            Ss[r * ATTN_SW + lane]      = v0;
            Ss[r * ATTN_SW + lane + 32] = v1;
            float t = v0 + v1;
#pragma unroll
            for (int o = 16; o; o >>= 1) t += __shfl_xor_sync(0xffffffffu, t, o);
            if (lane == 0) lsum[r] += t;
        }
        __syncthreads();

        // ---- O += P V ----
#pragma unroll 2
        for (int kk = 0; kk < 64; kk++) {
            float p[4];
#pragma unroll
            for (int i = 0; i < 4; i++) p[i] = Ss[(ty * 4 + i) * ATTN_SW + kk];
            float v[16];
            const float* vr = Vs + kk * FF + tx * 16;
            *(float4*)(v + 0)  = *(const float4*)(vr + 0);
            *(float4*)(v + 4)  = *(const float4*)(vr + 4);
            *(float4*)(v + 8)  = *(const float4*)(vr + 8);
            *(float4*)(v + 12) = *(const float4*)(vr + 12);
#pragma unroll
            for (int i = 0; i < 4; i++)
#pragma unroll
                for (int c = 0; c < 16; c++)
                    acc[i][c] = fmaf(p[i], v[c], acc[i][c]);
        }
        __syncthreads();
    }

    // ---- epilogue: normalize + bias, write cols 256..511 ----
    float* outb = out + ((size_t)b * NN + m0) * OUTW + 256;
#pragma unroll
    for (int i = 0; i < 4; i++) {
        int r = ty * 4 + i;
        float inv = 1.0f / lsum[r];
#pragma unroll
        for (int c4 = 0; c4 < 4; c4++) {
            int c = tx * 16 + c4 * 4;
            float4 o;
            o.x = acc[i][c4 * 4 + 0] * inv + bias[c + 0];
            o.y = acc[i][c4 * 4 + 1] * inv + bias[c + 1];
            o.z = acc[i][c4 * 4 + 2] * inv + bias[c + 2];
            o.w = acc[i][c4 * 4 + 3] * inv + bias[c + 3];
            *(float4*)(outb + (size_t)r * OUTW + c) = o;
        }
    }
}

// ---------------- launcher ---------------------------------------------------
extern "C" void kernel_launch(void* const* d_in, const int* in_sizes, int n_in,
                              void* d_out, int out_size) {
    const float* x          = (const float*)d_in[0];
    const int*   H          = (const int*)  d_in[1];
    const float* weight     = (const float*)d_in[2];
    const float* bias       = (const float*)d_in[3];
    const float* Wn_w       = (const float*)d_in[4];
    const float* Wn_b       = (const float*)d_in[5];
    const float* m1_w       = (const float*)d_in[6];
    const float* m1_b       = (const float*)d_in[7];
    const float* m2_w       = (const float*)d_in[8];
    const float* m2_b       = (const float*)d_in[9];
    const float* m3_w       = (const float*)d_in[10];
    const float* m3_b       = (const float*)d_in[11];
    const float* c_w        = (const float*)d_in[12];
    const float* c_b        = (const float*)d_in[13];
    const float* hedge_bias = (const float*)d_in[14];
    const float* alpha      = (const float*)d_in[15];
    float* out = (float*)d_out;

    cudaFuncSetAttribute(proj_kernel, cudaFuncAttributeMaxDynamicSharedMemorySize, PROJ_SMEM);
    cudaFuncSetAttribute(attn_kernel, cudaFuncAttributeMaxDynamicSharedMemorySize, ATTN_SMEM);

    proj_kernel<<<256, 256, PROJ_SMEM>>>(x, Wn_w, Wn_b, weight);
    transpose_kernel<<<dim3(128, 8, 4), dim3(32, 8)>>>();
    hedge_kernel<<<dim3(MAXE, BB), 256>>>(x, H, m1_w, m1_b, m2_w, m2_b, m3_w, m3_b);
    gamma_kernel<<<dim3(NN, BB), 256>>>(x, H, c_w, c_b, hedge_bias, alpha, out);
    attn_kernel<<<dim3(NN / 64, BB), 256, ATTN_SMEM>>>(bias, out);
}

// round 3
// speedup vs baseline: 5.2042x; 5.2042x over previous
#include <cuda_runtime.h>
#include <cuda_bf16.h>
#include <cstdint>
#include <math.h>

#define BB 4
#define NN 4096
#define EE 256
#define FF 256
#define MAXE 50
#define OUTW 512

// ---------------- scratch (device globals: allocation-free) ----------------
__device__ __nv_bfloat16 g_xpH[BB * NN * FF];  // bf16(x @ Wn_w + Wn_b)  (Q and K)
__device__ float         g_xw [BB * NN * FF];  // x @ weight             (V, tf32)
__device__ float         g_ctx[BB * MAXE];
__device__ int           g_deg[MAXE];

// ======================= helpers ============================================
__device__ __forceinline__ uint32_t smem_u32(const void* p) {
    uint32_t a;
    asm("{ .reg .u64 t; cvta.to.shared.u64 t, %1; cvt.u32.u64 %0, t; }" : "=r"(a) : "l"(p));
    return a;
}
__device__ __forceinline__ void cpasync16(uint32_t dst, const void* src) {
    asm volatile("cp.async.cg.shared.global [%0], [%1], 16;" :: "r"(dst), "l"(src));
}
#define CP_COMMIT() asm volatile("cp.async.commit_group;" ::: "memory")
#define CP_WAIT0()  asm volatile("cp.async.wait_group 0;" ::: "memory")

__device__ __forceinline__ void mma_bf16(float* d, const uint32_t* a, const uint32_t* b) {
    asm volatile("mma.sync.aligned.m16n8k16.row.col.f32.bf16.bf16.f32 "
        "{%0,%1,%2,%3}, {%4,%5,%6,%7}, {%8,%9}, {%0,%1,%2,%3};"
        : "+f"(d[0]), "+f"(d[1]), "+f"(d[2]), "+f"(d[3])
        : "r"(a[0]), "r"(a[1]), "r"(a[2]), "r"(a[3]), "r"(b[0]), "r"(b[1]));
}
__device__ __forceinline__ void mma_tf32(float* d, const uint32_t* a, const uint32_t* b) {
    asm volatile("mma.sync.aligned.m16n8k8.row.col.f32.tf32.tf32.f32 "
        "{%0,%1,%2,%3}, {%4,%5,%6,%7}, {%8,%9}, {%0,%1,%2,%3};"
        : "+f"(d[0]), "+f"(d[1]), "+f"(d[2]), "+f"(d[3])
        : "r"(a[0]), "r"(a[1]), "r"(a[2]), "r"(a[3]), "r"(b[0]), "r"(b[1]));
}

// ---------------- kernel 1: fused projections (xp->bf16, xw->f32) -----------
#define PROJ_SMEM ((64 * 256 + 32 * 256) * 4)

__global__ void __launch_bounds__(256, 2)
proj_kernel(const float* __restrict__ x,
            const float* __restrict__ Wn_w, const float* __restrict__ Wn_b,
            const float* __restrict__ weight) {
    extern __shared__ float sm[];
    float* xs = sm;            // [64][256]
    float* ws = sm + 64 * 256; // [32][256]
    const int row0 = blockIdx.x * 64;
    const int tid = threadIdx.x;
    const int ty = tid >> 4, tx = tid & 15;

    {
        const float4* src = (const float4*)(x + (size_t)row0 * FF);
        float4* dst = (float4*)xs;
#pragma unroll
        for (int i = 0; i < 16; i++) dst[tid + i * 256] = src[tid + i * 256];
    }

    for (int wsel = 0; wsel < 2; wsel++) {
        const float* W = wsel ? weight : Wn_w;
        float acc[4][16];
#pragma unroll
        for (int i = 0; i < 4; i++)
#pragma unroll
            for (int c = 0; c < 16; c++) acc[i][c] = 0.f;

        for (int ko = 0; ko < FF; ko += 32) {
            __syncthreads();
            {
                const float4* wsrc = (const float4*)(W + (size_t)ko * FF);
                float4* wdst = (float4*)ws;
#pragma unroll
                for (int i = 0; i < 8; i++) wdst[tid + i * 256] = wsrc[tid + i * 256];
            }
            __syncthreads();
#pragma unroll 2
            for (int kk = 0; kk < 32; kk++) {
                float p[4];
#pragma unroll
                for (int i = 0; i < 4; i++) p[i] = xs[(ty * 4 + i) * FF + ko + kk];
                float v[16];
                const float* vr = ws + kk * FF + tx * 16;
                *(float4*)(v + 0)  = *(const float4*)(vr + 0);
                *(float4*)(v + 4)  = *(const float4*)(vr + 4);
                *(float4*)(v + 8)  = *(const float4*)(vr + 8);
                *(float4*)(v + 12) = *(const float4*)(vr + 12);
#pragma unroll
                for (int i = 0; i < 4; i++)
#pragma unroll
                    for (int c = 0; c < 16; c++)
                        acc[i][c] = fmaf(p[i], v[c], acc[i][c]);
            }
        }
#pragma unroll
        for (int i = 0; i < 4; i++) {
            size_t r = (size_t)row0 + ty * 4 + i;
#pragma unroll
            for (int c4 = 0; c4 < 4; c4++) {
                int c = tx * 16 + c4 * 4;
                if (wsel == 0) {
                    float o0 = acc[i][c4 * 4 + 0] + Wn_b[c + 0];
                    float o1 = acc[i][c4 * 4 + 1] + Wn_b[c + 1];
                    float o2 = acc[i][c4 * 4 + 2] + Wn_b[c + 2];
                    float o3 = acc[i][c4 * 4 + 3] + Wn_b[c + 3];
                    __nv_bfloat16* dst = g_xpH + r * FF + c;
                    *(__nv_bfloat162*)(dst + 0) = __floats2bfloat162_rn(o0, o1);
                    *(__nv_bfloat162*)(dst + 2) = __floats2bfloat162_rn(o2, o3);
                } else {
                    float4 o;
                    o.x = acc[i][c4 * 4 + 0];
                    o.y = acc[i][c4 * 4 + 1];
                    o.z = acc[i][c4 * 4 + 2];
                    o.w = acc[i][c4 * 4 + 3];
                    *(float4*)(g_xw + r * FF + c) = o;
                }
            }
        }
    }
}

// ---------------- kernel 3: hyperedge branch ---------------------------------
__global__ void hedge_kernel(const float* __restrict__ x, const int* __restrict__ H,
                             const float* __restrict__ m1_w, const float* __restrict__ m1_b,
                             const float* __restrict__ m2_w, const float* __restrict__ m2_b,
                             const float* __restrict__ m3_w, const float* __restrict__ m3_b) {
    __shared__ int   flags[256];
    __shared__ float mean[FF];
    __shared__ float h1[128];
    __shared__ float h2[64];
    const int e = blockIdx.x;
    const int b = blockIdx.y;
    const int tid = threadIdx.x;
    const float* xb = x + (size_t)b * NN * FF;

    float a = 0.f;
    int deg = 0;
    for (int n0 = 0; n0 < NN; n0 += 256) {
        __syncthreads();
        flags[tid] = H[(size_t)(n0 + tid) * EE + e];
        __syncthreads();
#pragma unroll 8
        for (int j = 0; j < 256; j++) {
            deg += flags[j];
            if (flags[j]) a += xb[(size_t)(n0 + j) * FF + tid];
        }
    }
    mean[tid] = a / fmaxf((float)deg, 1.0f);
    __syncthreads();

    if (tid < 128) {
        float s = m1_b[tid];
#pragma unroll 4
        for (int k = 0; k < 256; k++) s = fmaf(mean[k], m1_w[k * 128 + tid], s);
        h1[tid] = fmaxf(s, 0.f);
    }
    __syncthreads();
    if (tid < 64) {
        float s = m2_b[tid];
#pragma unroll 4
        for (int k = 0; k < 128; k++) s = fmaf(h1[k], m2_w[k * 64 + tid], s);
        h2[tid] = fmaxf(s, 0.f);
    }
    __syncthreads();
    if (tid == 0) {
        float s = m3_b[0];
        for (int k = 0; k < 64; k++) s = fmaf(h2[k], m3_w[k], s);
        g_ctx[b * MAXE + e] = s;
        if (b == 0) g_deg[e] = deg;
    }
}

// ---------------- kernel 4: adaptive weights (output cols 0..255) ------------
__global__ void gamma_kernel(const float* __restrict__ x, const int* __restrict__ H,
                             const float* __restrict__ c_w, const float* __restrict__ c_b,
                             const float* __restrict__ hedge_bias, const float* __restrict__ alpha,
                             float* __restrict__ out) {
    __shared__ float red[8];
    const int n = blockIdx.x, b = blockIdx.y;
    const int tid = threadIdx.x;
    const int lane = tid & 31, warp = tid >> 5;

    float v = x[((size_t)b * NN + n) * FF + tid] * c_w[tid];
#pragma unroll
    for (int o = 16; o; o >>= 1) v += __shfl_xor_sync(0xffffffffu, v, o);
    if (lane == 0) red[warp] = v;
    __syncthreads();
    float compat = red[0] + red[1] + red[2] + red[3] + red[4] + red[5] + red[6] + red[7];
    compat += c_b[0] + hedge_bias[0];

    float o = 0.f;
    if (tid < MAXE) {
        if (g_deg[tid] > 1 && H[(size_t)n * EE + tid] != 0) {
            float z = compat + alpha[0] * g_ctx[b * MAXE + tid];
            o = 1.0f / (1.0f + expf(-z));
        }
    }
    out[((size_t)b * NN + n) * OUTW + tid] = o;
}

// ---------------- kernel 5: mma.sync attention -------------------------------
// BM=128, BN=32, 8 warps (4m x 2n). Q bf16 resident; K bf16 + V f32 double-buffered
// via cp.async. S in bf16 mma (m16n8k16), PV in tf32 mma (m16n8k8), P via smem.
// strides: 264 elems (bank-conflict-free fragment loads).
#define QS 0
#define KS (QS + 128 * 264 * 2)        // 67584
#define VSOFF (KS + 2 * 32 * 264 * 2)  // +33792 = 101376
#define PSOFF (VSOFF + 2 * 32 * 264 * 4) // +67584 = 168960
#define LSOFF (PSOFF + 128 * 36 * 4)   // +18432 = 187392
#define ATTN_SMEM (LSOFF + 512)        // 187904
#define KBUFB 16896                    // 32*264*2
#define VBUFB 33792                    // 32*264*4

__global__ void __launch_bounds__(256)
attn_kernel(const float* __restrict__ bias, float* __restrict__ out) {
    extern __shared__ char smc[];
    const uint32_t sb = smem_u32(smc);
    __nv_bfloat16* Qs = (__nv_bfloat16*)(smc + QS);
    __nv_bfloat16* Ksm = (__nv_bfloat16*)(smc + KS);
    float* Vsm = (float*)(smc + VSOFF);
    float* Ps  = (float*)(smc + PSOFF);
    float* Lsm = (float*)(smc + LSOFF);

    const int tid = threadIdx.x;
    const int wid = tid >> 5, lane = tid & 31;
    const int g = lane >> 2, t = lane & 3;
    const int wm = wid & 3, wn = wid >> 2;
    const int b = blockIdx.y;
    const int m0 = blockIdx.x * 128;

    const __nv_bfloat16* gK = g_xpH + (size_t)b * NN * FF;
    const float*         gV = g_xw  + (size_t)b * NN * FF;

    // ---- prologue: Q (one-time) + K0/V0 via cp.async ----
#pragma unroll
    for (int it = 0; it < 16; it++) {
        int id = tid + it * 256;
        int row = id >> 5, c = id & 31;
        cpasync16(sb + QS + row * 528 + c * 16,
                  (const char*)(gK + (size_t)(m0 + row) * FF) + c * 16);
    }
#pragma unroll
    for (int it = 0; it < 4; it++) {
        int id = tid + it * 256;
        int row = id >> 5, c = id & 31;
        cpasync16(sb + KS + row * 528 + c * 16,
                  (const char*)(gK + (size_t)row * FF) + c * 16);
    }
#pragma unroll
    for (int it = 0; it < 8; it++) {
        int id = tid + it * 256;
        int row = id >> 6, c = id & 63;
        cpasync16(sb + VSOFF + row * 1056 + c * 16,
                  (const char*)(gV + (size_t)row * FF) + c * 16);
    }
    CP_COMMIT();
    if (tid < 128) Lsm[tid] = 0.f;
    CP_WAIT0();
    __syncthreads();

    float o[2][16][4];
#pragma unroll
    for (int mi = 0; mi < 2; mi++)
#pragma unroll
        for (int ni = 0; ni < 16; ni++)
#pragma unroll
            for (int f = 0; f < 4; f++) o[mi][ni][f] = 0.f;
    float lsum[2][2] = {{0.f, 0.f}, {0.f, 0.f}};

#pragma unroll 1
    for (int j = 0; j < 128; j++) {
        const int buf = j & 1;
        // prefetch j+1 into buf^1
        if (j + 1 < 128) {
            const int j0 = (j + 1) * 32;
            const int pb = buf ^ 1;
#pragma unroll
            for (int it = 0; it < 4; it++) {
                int id = tid + it * 256;
                int row = id >> 5, c = id & 31;
                cpasync16(sb + KS + pb * KBUFB + row * 528 + c * 16,
                          (const char*)(gK + (size_t)(j0 + row) * FF) + c * 16);
            }
#pragma unroll
            for (int it = 0; it < 8; it++) {
                int id = tid + it * 256;
                int row = id >> 6, c = id & 63;
                cpasync16(sb + VSOFF + pb * VBUFB + row * 1056 + c * 16,
                          (const char*)(gV + (size_t)(j0 + row) * FF) + c * 16);
            }
        }
        CP_COMMIT();

        // ---- S = Q K^T (bf16 mma) ----
        float s[2][2][4];
#pragma unroll
        for (int mi = 0; mi < 2; mi++)
#pragma unroll
            for (int ni = 0; ni < 2; ni++)
#pragma unroll
                for (int f = 0; f < 4; f++) s[mi][ni][f] = 0.f;

        const __nv_bfloat16* kb = Ksm + buf * (32 * 264);
#pragma unroll
        for (int kk = 0; kk < 16; kk++) {
            uint32_t a[2][4];
#pragma unroll
            for (int mi = 0; mi < 2; mi++) {
                const __nv_bfloat16* qp = Qs + (wm * 32 + mi * 16) * 264 + kk * 16;
                a[mi][0] = *(const uint32_t*)(qp + (size_t)g * 264 + 2 * t);
                a[mi][1] = *(const uint32_t*)(qp + (size_t)(g + 8) * 264 + 2 * t);
                a[mi][2] = *(const uint32_t*)(qp + (size_t)g * 264 + 2 * t + 8);
                a[mi][3] = *(const uint32_t*)(qp + (size_t)(g + 8) * 264 + 2 * t + 8);
            }
#pragma unroll
            for (int ni = 0; ni < 2; ni++) {
                const __nv_bfloat16* kp = kb + (wn * 16 + ni * 8 + g) * 264 + kk * 16;
                uint32_t bb[2];
                bb[0] = *(const uint32_t*)(kp + 2 * t);
                bb[1] = *(const uint32_t*)(kp + 2 * t + 8);
                mma_bf16(s[0][ni], a[0], bb);
                mma_bf16(s[1][ni], a[1], bb);
            }
        }

        // ---- exp, row partial sums, store P ----
        float rs[2][2] = {{0.f, 0.f}, {0.f, 0.f}};
#pragma unroll
        for (int mi = 0; mi < 2; mi++) {
#pragma unroll
            for (int ni = 0; ni < 2; ni++) {
#pragma unroll
                for (int f = 0; f < 4; f++)
                    s[mi][ni][f] = __expf(s[mi][ni][f] * 0.0625f);
                rs[mi][0] += s[mi][ni][0] + s[mi][ni][1];
                rs[mi][1] += s[mi][ni][2] + s[mi][ni][3];
                float* pp = Ps + (wm * 32 + mi * 16) * 36 + wn * 16 + ni * 8 + 2 * t;
                float2 lo; lo.x = s[mi][ni][0]; lo.y = s[mi][ni][1];
                float2 hi; hi.x = s[mi][ni][2]; hi.y = s[mi][ni][3];
                *(float2*)(pp + (size_t)g * 36) = lo;
                *(float2*)(pp + (size_t)(g + 8) * 36) = hi;
            }
#pragma unroll
            for (int h = 0; h < 2; h++) {
                float v = rs[mi][h];
                v += __shfl_xor_sync(0xffffffffu, v, 1);
                v += __shfl_xor_sync(0xffffffffu, v, 2);
                lsum[mi][h] += v;
            }
        }
        __syncthreads();

        // ---- O += P V (tf32 mma) ----
        const float* vb = Vsm + buf * (32 * 264);
#pragma unroll
        for (int ks = 0; ks < 4; ks++) {
            uint32_t a[2][4];
#pragma unroll
            for (int mi = 0; mi < 2; mi++) {
                const float* pp = Ps + (wm * 32 + mi * 16) * 36 + ks * 8;
                a[mi][0] = __float_as_uint(pp[(size_t)g * 36 + t]);
                a[mi][1] = __float_as_uint(pp[(size_t)(g + 8) * 36 + t]);
                a[mi][2] = __float_as_uint(pp[(size_t)g * 36 + t + 4]);
                a[mi][3] = __float_as_uint(pp[(size_t)(g + 8) * 36 + t + 4]);
            }
#pragma unroll
            for (int ni = 0; ni < 16; ni++) {
                const float* vp = vb + (ks * 8 + t) * 264 + wn * 128 + ni * 8 + g;
                uint32_t bb[2];
                bb[0] = __float_as_uint(vp[0]);
                bb[1] = __float_as_uint(vp[4 * 264]);
                mma_tf32(o[0][ni], a[0], bb);
                mma_tf32(o[1][ni], a[1], bb);
            }
        }
        CP_WAIT0();
        __syncthreads();
    }

    // ---- combine row sums (2 deterministic addends per row) ----
    if (t == 0) {
#pragma unroll
        for (int mi = 0; mi < 2; mi++)
#pragma unroll
            for (int h = 0; h < 2; h++)
                atomicAdd(&Lsm[wm * 32 + mi * 16 + g + 8 * h], lsum[mi][h]);
    }
    __syncthreads();

    // ---- epilogue: normalize + bias ----
#pragma unroll
    for (int mi = 0; mi < 2; mi++) {
        const int r0 = wm * 32 + mi * 16 + g;
        const float i0 = 1.0f / Lsm[r0];
        const float i1 = 1.0f / Lsm[r0 + 8];
        float* orow0 = out + ((size_t)b * NN + m0 + r0) * OUTW + 256;
        float* orow1 = orow0 + (size_t)8 * OUTW;
#pragma unroll
        for (int ni = 0; ni < 16; ni++) {
            const int col = wn * 128 + ni * 8 + 2 * t;
            float2 v0, v1;
            v0.x = o[mi][ni][0] * i0 + bias[col];
            v0.y = o[mi][ni][1] * i0 + bias[col + 1];
            v1.x = o[mi][ni][2] * i1 + bias[col];
            v1.y = o[mi][ni][3] * i1 + bias[col + 1];
            *(float2*)(orow0 + col) = v0;
            *(float2*)(orow1 + col) = v1;
        }
    }
}

// ---------------- launcher ---------------------------------------------------
extern "C" void kernel_launch(void* const* d_in, const int* in_sizes, int n_in,
                              void* d_out, int out_size) {
    const float* x          = (const float*)d_in[0];
    const int*   H          = (const int*)  d_in[1];
    const float* weight     = (const float*)d_in[2];
    const float* bias       = (const float*)d_in[3];
    const float* Wn_w       = (const float*)d_in[4];
    const float* Wn_b       = (const float*)d_in[5];
    const float* m1_w       = (const float*)d_in[6];
    const float* m1_b       = (const float*)d_in[7];
    const float* m2_w       = (const float*)d_in[8];
    const float* m2_b       = (const float*)d_in[9];
    const float* m3_w       = (const float*)d_in[10];
    const float* m3_b       = (const float*)d_in[11];
    const float* c_w        = (const float*)d_in[12];
    const float* c_b        = (const float*)d_in[13];
    const float* hedge_bias = (const float*)d_in[14];
    const float* alpha      = (const float*)d_in[15];
    float* out = (float*)d_out;

    cudaFuncSetAttribute(proj_kernel, cudaFuncAttributeMaxDynamicSharedMemorySize, PROJ_SMEM);
    cudaFuncSetAttribute(attn_kernel, cudaFuncAttributeMaxDynamicSharedMemorySize, ATTN_SMEM);

    proj_kernel<<<256, 256, PROJ_SMEM>>>(x, Wn_w, Wn_b, weight);
    hedge_kernel<<<dim3(MAXE, BB), 256>>>(x, H, m1_w, m1_b, m2_w, m2_b, m3_w, m3_b);
    gamma_kernel<<<dim3(NN, BB), 256>>>(x, H, c_w, c_b, hedge_bias, alpha, out);
    attn_kernel<<<dim3(NN / 128, BB), 256, ATTN_SMEM>>>(bias, out);
}

// round 7
// speedup vs baseline: 9.5946x; 1.8436x over previous
#include <cuda_runtime.h>
#include <cuda_bf16.h>
#include <cuda_fp16.h>
#include <cstdint>
#include <math.h>

#define BB 4
#define NN 4096
#define EE 256
#define FF 256
#define MAXE 50
#define OUTW 512

// ---------------- scratch (device globals: allocation-free) ----------------
__device__ __nv_bfloat16 g_xpH[BB * NN * FF];  // bf16(x @ Wn_w + Wn_b)  (Q,K)
__device__ __half        g_xwH[BB * NN * FF];  // fp16(x @ weight)       (V)
__device__ float         g_ctx[BB * MAXE];
__device__ int           g_deg[MAXE];

// ======================= helpers ============================================
__device__ __forceinline__ uint32_t smem_u32(const void* p) {
    uint32_t a;
    asm("{ .reg .u64 t; cvta.to.shared.u64 t, %1; cvt.u32.u64 %0, t; }" : "=r"(a) : "l"(p));
    return a;
}
__device__ __forceinline__ void cpasync16(uint32_t dst, const void* src) {
    asm volatile("cp.async.cg.shared.global [%0], [%1], 16;" :: "r"(dst), "l"(src));
}
#define CP_COMMIT() asm volatile("cp.async.commit_group;" ::: "memory")
#define CP_WAIT0()  asm volatile("cp.async.wait_group 0;" ::: "memory")
#define CP_WAIT1()  asm volatile("cp.async.wait_group 1;" ::: "memory")

#define LDSM_X4(r, addr) \
    asm volatile("ldmatrix.sync.aligned.m8n8.x4.shared.b16 {%0,%1,%2,%3}, [%4];" \
        : "=r"((r)[0]), "=r"((r)[1]), "=r"((r)[2]), "=r"((r)[3]) : "r"(addr))
#define LDSM_X4T(r, addr) \
    asm volatile("ldmatrix.sync.aligned.m8n8.x4.trans.shared.b16 {%0,%1,%2,%3}, [%4];" \
        : "=r"((r)[0]), "=r"((r)[1]), "=r"((r)[2]), "=r"((r)[3]) : "r"(addr))

__device__ __forceinline__ void mma_bf16(float* d, const uint32_t* a, const uint32_t* b) {
    asm volatile("mma.sync.aligned.m16n8k16.row.col.f32.bf16.bf16.f32 "
        "{%0,%1,%2,%3}, {%4,%5,%6,%7}, {%8,%9}, {%0,%1,%2,%3};"
        : "+f"(d[0]), "+f"(d[1]), "+f"(d[2]), "+f"(d[3])
        : "r"(a[0]), "r"(a[1]), "r"(a[2]), "r"(a[3]), "r"(b[0]), "r"(b[1]));
}
__device__ __forceinline__ void mma_f16(float* d, const uint32_t* a, const uint32_t* b) {
    asm volatile("mma.sync.aligned.m16n8k16.row.col.f32.f16.f16.f32 "
        "{%0,%1,%2,%3}, {%4,%5,%6,%7}, {%8,%9}, {%0,%1,%2,%3};"
        : "+f"(d[0]), "+f"(d[1]), "+f"(d[2]), "+f"(d[3])
        : "r"(a[0]), "r"(a[1]), "r"(a[2]), "r"(a[3]), "r"(b[0]), "r"(b[1]));
}
__device__ __forceinline__ void mma_tf32(float* d, const uint32_t* a, const uint32_t* b) {
    asm volatile("mma.sync.aligned.m16n8k8.row.col.f32.tf32.tf32.f32 "
        "{%0,%1,%2,%3}, {%4,%5,%6,%7}, {%8,%9}, {%0,%1,%2,%3};"
        : "+f"(d[0]), "+f"(d[1]), "+f"(d[2]), "+f"(d[3])
        : "r"(a[0]), "r"(a[1]), "r"(a[2]), "r"(a[3]), "r"(b[0]), "r"(b[1]));
}

// ---------------- kernel 1: projections via tf32 mma.sync --------------------
// BM=128, 256 threads (warps 4m x 2n). K chunks of 64, smem xs[128][68] + ws[64][264].
#define PJ_XS 0
#define PJ_WS (128 * 68 * 4)                 // 34816
#define PROJ_SMEM (PJ_WS + 64 * 264 * 4)     // 102400

__global__ void __launch_bounds__(256)
proj_kernel(const float* __restrict__ x,
            const float* __restrict__ Wn_w, const float* __restrict__ Wn_b,
            const float* __restrict__ weight) {
    extern __shared__ char smc[];
    const uint32_t sb = smem_u32(smc);
    float* xs = (float*)(smc + PJ_XS);   // [128][68]
    float* ws = (float*)(smc + PJ_WS);   // [64][264]

    const int tid = threadIdx.x;
    const int wid = tid >> 5, lane = tid & 31;
    const int g = lane >> 2, t = lane & 3;
    const int wm = wid & 3, wn = wid >> 2;
    const size_t row0 = (size_t)blockIdx.x * 128;
    const char* xg = (const char*)(x + row0 * FF);

    for (int wsel = 0; wsel < 2; wsel++) {
        const float* W = wsel ? weight : Wn_w;
        float o[2][16][4];
#pragma unroll
        for (int mi = 0; mi < 2; mi++)
#pragma unroll
            for (int ni = 0; ni < 16; ni++)
#pragma unroll
                for (int f = 0; f < 4; f++) o[mi][ni][f] = 0.f;

        for (int kc = 0; kc < 4; kc++) {
            __syncthreads();
            // x chunk: 128 rows x 64 f32
#pragma unroll
            for (int it = 0; it < 8; it++) {
                int id = tid + it * 256;
                int r = id >> 4, c = id & 15;
                cpasync16(sb + PJ_XS + r * 272 + c * 16, xg + (size_t)r * 1024 + kc * 256 + c * 16);
            }
            // W chunk: 64 rows x 256 f32
#pragma unroll
            for (int it = 0; it < 16; it++) {
                int id = tid + it * 256;
                int r = id >> 6, c = id & 63;
                cpasync16(sb + PJ_WS + r * 1056 + c * 16,
                          (const char*)(W + (size_t)(kc * 64 + r) * FF) + c * 16);
            }
            CP_COMMIT(); CP_WAIT0();
            __syncthreads();
#pragma unroll
            for (int ks = 0; ks < 8; ks++) {
                uint32_t a[2][4];
#pragma unroll
                for (int mi = 0; mi < 2; mi++) {
                    const float* ap = xs + (wm * 32 + mi * 16) * 68 + ks * 8;
                    a[mi][0] = __float_as_uint(ap[(size_t)g * 68 + t]);
                    a[mi][1] = __float_as_uint(ap[(size_t)(g + 8) * 68 + t]);
                    a[mi][2] = __float_as_uint(ap[(size_t)g * 68 + t + 4]);
                    a[mi][3] = __float_as_uint(ap[(size_t)(g + 8) * 68 + t + 4]);
                }
#pragma unroll
                for (int ni = 0; ni < 16; ni++) {
                    const float* bp = ws + (ks * 8 + t) * 264 + wn * 128 + ni * 8 + g;
                    uint32_t bfr[2];
                    bfr[0] = __float_as_uint(bp[0]);
                    bfr[1] = __float_as_uint(bp[4 * 264]);
                    mma_tf32(o[0][ni], a[0], bfr);
                    mma_tf32(o[1][ni], a[1], bfr);
                }
            }
        }
        // epilogue
#pragma unroll
        for (int mi = 0; mi < 2; mi++) {
            size_t r0 = row0 + wm * 32 + mi * 16 + g;
#pragma unroll
            for (int ni = 0; ni < 16; ni++) {
                int col = wn * 128 + ni * 8 + 2 * t;
                if (wsel == 0) {
                    float b0 = Wn_b[col], b1 = Wn_b[col + 1];
                    *(__nv_bfloat162*)(g_xpH + r0 * FF + col) =
                        __floats2bfloat162_rn(o[mi][ni][0] + b0, o[mi][ni][1] + b1);
                    *(__nv_bfloat162*)(g_xpH + (r0 + 8) * FF + col) =
                        __floats2bfloat162_rn(o[mi][ni][2] + b0, o[mi][ni][3] + b1);
                } else {
                    *(__half2*)(g_xwH + r0 * FF + col) =
                        __floats2half2_rn(o[mi][ni][0], o[mi][ni][1]);
                    *(__half2*)(g_xwH + (r0 + 8) * FF + col) =
                        __floats2half2_rn(o[mi][ni][2], o[mi][ni][3]);
                }
            }
        }
    }
}

// ---------------- kernel 3: hyperedge branch ---------------------------------
__global__ void hedge_kernel(const float* __restrict__ x, const int* __restrict__ H,
                             const float* __restrict__ m1_w, const float* __restrict__ m1_b,
                             const float* __restrict__ m2_w, const float* __restrict__ m2_b,
                             const float* __restrict__ m3_w, const float* __restrict__ m3_b) {
    __shared__ int   flags[256];
    __shared__ float mean[FF];
    __shared__ float h1[128];
    __shared__ float h2[64];
    const int e = blockIdx.x;
    const int b = blockIdx.y;
    const int tid = threadIdx.x;
    const float* xb = x + (size_t)b * NN * FF;

    float a = 0.f;
    int deg = 0;
    for (int n0 = 0; n0 < NN; n0 += 256) {
        __syncthreads();
        flags[tid] = H[(size_t)(n0 + tid) * EE + e];
        __syncthreads();
#pragma unroll 8
        for (int j = 0; j < 256; j++) {
            deg += flags[j];
            if (flags[j]) a += xb[(size_t)(n0 + j) * FF + tid];
        }
    }
    mean[tid] = a / fmaxf((float)deg, 1.0f);
    __syncthreads();

    if (tid < 128) {
        float s = m1_b[tid];
#pragma unroll 4
        for (int k = 0; k < 256; k++) s = fmaf(mean[k], m1_w[k * 128 + tid], s);
        h1[tid] = fmaxf(s, 0.f);
    }
    __syncthreads();
    if (tid < 64) {
        float s = m2_b[tid];
#pragma unroll 4
        for (int k = 0; k < 128; k++) s = fmaf(h1[k], m2_w[k * 64 + tid], s);
        h2[tid] = fmaxf(s, 0.f);
    }
    __syncthreads();
    if (tid == 0) {
        float s = m3_b[0];
        for (int k = 0; k < 64; k++) s = fmaf(h2[k], m3_w[k], s);
        g_ctx[b * MAXE + e] = s;
        if (b == 0) g_deg[e] = deg;
    }
}

// ---------------- kernel 4: adaptive weights (output cols 0..255) ------------
__global__ void gamma_kernel(const float* __restrict__ x, const int* __restrict__ H,
                             const float* __restrict__ c_w, const float* __restrict__ c_b,
                             const float* __restrict__ hedge_bias, const float* __restrict__ alpha,
                             float* __restrict__ out) {
    __shared__ float red[8];
    const int n = blockIdx.x, b = blockIdx.y;
    const int tid = threadIdx.x;
    const int lane = tid & 31, warp = tid >> 5;

    float v = x[((size_t)b * NN + n) * FF + tid] * c_w[tid];
#pragma unroll
    for (int o = 16; o; o >>= 1) v += __shfl_xor_sync(0xffffffffu, v, o);
    if (lane == 0) red[warp] = v;
    __syncthreads();
    float compat = red[0] + red[1] + red[2] + red[3] + red[4] + red[5] + red[6] + red[7];
    compat += c_b[0] + hedge_bias[0];

    float o = 0.f;
    if (tid < MAXE) {
        if (g_deg[tid] > 1 && H[(size_t)n * EE + tid] != 0) {
            float z = compat + alpha[0] * g_ctx[b * MAXE + tid];
            o = 1.0f / (1.0f + expf(-z));
        }
    }
    out[((size_t)b * NN + n) * OUTW + tid] = o;
}

// ---------------- kernel 5: mma attention (bf16 QK, fp16 PV, ldmatrix) -------
// BM=128, BN=32, 8 warps (4m x 2n). Q bf16 resident; K bf16, V fp16 double-buffered.
#define QS_B 0                              // bf16 [128][264]
#define KS_B 67584                          // bf16 2x[32][264]
#define VS_B 101376                         // fp16 2x[32][264]
#define PS_B 135168                         // fp16 [128][40]
#define LS_B 145408                         // f32  [128]
#define ATTN_SMEM 145920
#define KBUF_B 16896
#define VBUF_B 16896

__global__ void __launch_bounds__(256)
attn_kernel(const float* __restrict__ bias, float* __restrict__ out) {
    extern __shared__ char smc[];
    const uint32_t sb = smem_u32(smc);
    float* Lsm = (float*)(smc + LS_B);

    const int tid = threadIdx.x;
    const int wid = tid >> 5, lane = tid & 31;
    const int g = lane >> 2, t = lane & 3;
    const int wm = wid & 3, wn = wid >> 2;
    const int b = blockIdx.y;
    const int m0 = blockIdx.x * 128;

    const __nv_bfloat16* gK = g_xpH + (size_t)b * NN * FF;
    const __half*        gV = g_xwH + (size_t)b * NN * FF;

    // fragment base addresses (bytes)
    const uint32_t qbase = sb + QS_B +
        (uint32_t)(((wm * 32 + (lane & 15)) * 264 + (lane >> 4) * 8) * 2);
    // K fragment: warp wn covers key rows wn*16..wn*16+15  (FIX: + wn*16 rows)
    const uint32_t koff = (uint32_t)(wn * 16 * 528) +
        (uint32_t)((((lane & 7) + ((lane >> 4) & 1) * 8) * 264 +
                    ((lane >> 3) & 1) * 8) * 2);
    const uint32_t pbase = sb + PS_B +
        (uint32_t)(((wm * 32 + (lane & 15)) * 40 + (lane >> 4) * 8) * 2);
    const uint32_t voff = (uint32_t)(((lane & 7) + ((lane >> 3) & 1) * 8) * 528 +
                                     (wn * 128 + ((lane >> 4) & 1) * 8) * 2);
    const uint32_t pst0 = sb + PS_B + (uint32_t)(((wm * 32 + g) * 40 + wn * 16 + 2 * t) * 2);

    // ---- prologue: Q + K0/V0 (group 0) ----
#pragma unroll
    for (int it = 0; it < 16; it++) {
        int id = tid + it * 256;
        int r = id >> 5, c = id & 31;
        cpasync16(sb + QS_B + r * 528 + c * 16,
                  (const char*)(gK + (size_t)(m0 + r) * FF) + c * 16);
    }
#pragma unroll
    for (int it = 0; it < 4; it++) {
        int id = tid + it * 256;
        int r = id >> 5, c = id & 31;
        cpasync16(sb + KS_B + r * 528 + c * 16, (const char*)(gK + (size_t)r * FF) + c * 16);
        cpasync16(sb + VS_B + r * 528 + c * 16, (const char*)(gV + (size_t)r * FF) + c * 16);
    }
    CP_COMMIT();
    if (tid < 128) Lsm[tid] = 0.f;

    float o[2][16][4];
#pragma unroll
    for (int mi = 0; mi < 2; mi++)
#pragma unroll
        for (int ni = 0; ni < 16; ni++)
#pragma unroll
            for (int f = 0; f < 4; f++) o[mi][ni][f] = 0.f;
    float lsum[2][2] = {{0.f, 0.f}, {0.f, 0.f}};

#pragma unroll 1
    for (int j = 0; j < 128; j++) {
        // prefetch j+1 into buf (j+1)&1
        if (j + 1 < 128) {
            const int j0 = (j + 1) * 32;
            const uint32_t kb = sb + KS_B + ((j + 1) & 1) * KBUF_B;
            const uint32_t vb = sb + VS_B + ((j + 1) & 1) * VBUF_B;
#pragma unroll
            for (int it = 0; it < 4; it++) {
                int id = tid + it * 256;
                int r = id >> 5, c = id & 31;
                cpasync16(kb + r * 528 + c * 16,
                          (const char*)(gK + (size_t)(j0 + r) * FF) + c * 16);
                cpasync16(vb + r * 528 + c * 16,
                          (const char*)(gV + (size_t)(j0 + r) * FF) + c * 16);
            }
        }
        CP_COMMIT();
        CP_WAIT1();               // buf j (and Q) ready
        __syncthreads();

        // ---- S = Q K^T (bf16, ldmatrix) ----
        float s[2][2][4];
#pragma unroll
        for (int mi = 0; mi < 2; mi++)
#pragma unroll
            for (int ni = 0; ni < 2; ni++)
#pragma unroll
                for (int f = 0; f < 4; f++) s[mi][ni][f] = 0.f;

        const uint32_t kbb = sb + KS_B + (j & 1) * KBUF_B + koff;
#pragma unroll
        for (int kk = 0; kk < 16; kk++) {
            uint32_t qa[2][4], kf[4];
            LDSM_X4(qa[0], qbase + kk * 32);
            LDSM_X4(qa[1], qbase + 16 * 528 + kk * 32);
            LDSM_X4(kf, kbb + kk * 32);
            mma_bf16(s[0][0], qa[0], kf + 0);
            mma_bf16(s[0][1], qa[0], kf + 2);
            mma_bf16(s[1][0], qa[1], kf + 0);
            mma_bf16(s[1][1], qa[1], kf + 2);
        }

        // ---- exp, partial row sums, store P (fp16) ----
        float rs[2][2] = {{0.f, 0.f}, {0.f, 0.f}};
#pragma unroll
        for (int mi = 0; mi < 2; mi++) {
#pragma unroll
            for (int ni = 0; ni < 2; ni++) {
                float p0 = __expf(s[mi][ni][0] * 0.0625f);
                float p1 = __expf(s[mi][ni][1] * 0.0625f);
                float p2 = __expf(s[mi][ni][2] * 0.0625f);
                float p3 = __expf(s[mi][ni][3] * 0.0625f);
                rs[mi][0] += p0 + p1;
                rs[mi][1] += p2 + p3;
                uint32_t pa = pst0 + mi * 16 * 80 + ni * 16;
                __half2 h0 = __floats2half2_rn(p0, p1);
                __half2 h1 = __floats2half2_rn(p2, p3);
                asm volatile("st.shared.b32 [%0], %1;" :: "r"(pa), "r"(*(uint32_t*)&h0) : "memory");
                asm volatile("st.shared.b32 [%0], %1;" :: "r"(pa + 8 * 80), "r"(*(uint32_t*)&h1) : "memory");
            }
#pragma unroll
            for (int h = 0; h < 2; h++) {
                float v = rs[mi][h];
                v += __shfl_xor_sync(0xffffffffu, v, 1);
                v += __shfl_xor_sync(0xffffffffu, v, 2);
                lsum[mi][h] += v;
            }
        }
        __syncthreads();

        // ---- O += P V (fp16, ldmatrix) ----
        const uint32_t vbb = sb + VS_B + (j & 1) * VBUF_B + voff;
#pragma unroll
        for (int ks = 0; ks < 2; ks++) {
            uint32_t pa[2][4];
            LDSM_X4(pa[0], pbase + ks * 32);
            LDSM_X4(pa[1], pbase + 16 * 80 + ks * 32);
#pragma unroll
            for (int np = 0; np < 8; np++) {
                uint32_t vv[4];
                LDSM_X4T(vv, vbb + ks * 16 * 528 + np * 32);
                mma_f16(o[0][2 * np],     pa[0], vv + 0);
                mma_f16(o[0][2 * np + 1], pa[0], vv + 2);
                mma_f16(o[1][2 * np],     pa[1], vv + 0);
                mma_f16(o[1][2 * np + 1], pa[1], vv + 2);
            }
        }
        __syncthreads();   // buf j consumed; next iter overwrites it
    }

    // ---- combine row sums (2 deterministic addends per row) ----
    if (t == 0) {
#pragma unroll
        for (int mi = 0; mi < 2; mi++)
#pragma unroll
            for (int h = 0; h < 2; h++)
                atomicAdd(&Lsm[wm * 32 + mi * 16 + g + 8 * h], lsum[mi][h]);
    }
    __syncthreads();

    // ---- epilogue: normalize + bias ----
#pragma unroll
    for (int mi = 0; mi < 2; mi++) {
        const int r0 = wm * 32 + mi * 16 + g;
        const float i0 = 1.0f / Lsm[r0];
        const float i1 = 1.0f / Lsm[r0 + 8];
        float* orow0 = out + ((size_t)b * NN + m0 + r0) * OUTW + 256;
        float* orow1 = orow0 + (size_t)8 * OUTW;
#pragma unroll
        for (int ni = 0; ni < 16; ni++) {
            const int col = wn * 128 + ni * 8 + 2 * t;
            float2 v0, v1;
            v0.x = o[mi][ni][0] * i0 + bias[col];
            v0.y = o[mi][ni][1] * i0 + bias[col + 1];
            v1.x = o[mi][ni][2] * i1 + bias[col];
            v1.y = o[mi][ni][3] * i1 + bias[col + 1];
            *(float2*)(orow0 + col) = v0;
            *(float2*)(orow1 + col) = v1;
        }
    }
}

// ---------------- launcher ---------------------------------------------------
extern "C" void kernel_launch(void* const* d_in, const int* in_sizes, int n_in,
                              void* d_out, int out_size) {
    const float* x          = (const float*)d_in[0];
    const int*   H          = (const int*)  d_in[1];
    const float* weight     = (const float*)d_in[2];
    const float* bias       = (const float*)d_in[3];
    const float* Wn_w       = (const float*)d_in[4];
    const float* Wn_b       = (const float*)d_in[5];
    const float* m1_w       = (const float*)d_in[6];
    const float* m1_b       = (const float*)d_in[7];
    const float* m2_w       = (const float*)d_in[8];
    const float* m2_b       = (const float*)d_in[9];
    const float* m3_w       = (const float*)d_in[10];
    const float* m3_b       = (const float*)d_in[11];
    const float* c_w        = (const float*)d_in[12];
    const float* c_b        = (const float*)d_in[13];
    const float* hedge_bias = (const float*)d_in[14];
    const float* alpha      = (const float*)d_in[15];
    float* out = (float*)d_out;

    cudaFuncSetAttribute(proj_kernel, cudaFuncAttributeMaxDynamicSharedMemorySize, PROJ_SMEM);
    cudaFuncSetAttribute(attn_kernel, cudaFuncAttributeMaxDynamicSharedMemorySize, ATTN_SMEM);

    proj_kernel<<<128, 256, PROJ_SMEM>>>(x, Wn_w, Wn_b, weight);
    hedge_kernel<<<dim3(MAXE, BB), 256>>>(x, H, m1_w, m1_b, m2_w, m2_b, m3_w, m3_b);
    gamma_kernel<<<dim3(NN, BB), 256>>>(x, H, c_w, c_b, hedge_bias, alpha, out);
    attn_kernel<<<dim3(NN / 128, BB), 256, ATTN_SMEM>>>(bias, out);
}